// round 7
// baseline (speedup 1.0000x reference)
#include <cuda_runtime.h>
#include <math.h>

#define N_BINS 1024
#define NMASK  (N_BINS - 1)
#define DIM    512
#define DIM4   128            // DIM / 4 (float4 units)
#define NSTEPS 240
#define NK     122            // lags k in [-61, 60]
#define TI     8              // bins per block
#define NBLK   (N_BINS / TI)  // 128 blocks
#define RWIN   132            // window rows r'=0..131 (need 0..129)
#define NCHUNK 8              // K chunks of 64 floats
#define CHK4   16             // float4 per chunk per row
#define KC     8              // k-split groups
#define TG     2              // t-tile groups (4 t each)
#define RQ     33             // r-quads: rows rq, rq+33, rq+66, rq+99
#define NACT   (KC * TG * RQ) // 528 active threads
#define NTHREADS 544          // 17 warps
#define QBUF_F4 (RWIN * CHK4)         // 2112 float4 per Q buffer
#define DYN_BYTES (2 * QBUF_F4 * 16)  // 67584 B dynamic smem

// Scratch (device globals; no allocations allowed)
__device__ float g_bpart[NSTEPS * NBLK];   // per-(step, block) partial sums
__device__ unsigned g_ticket;              // last-block election (reset each launch)

union F4U2 { float4 f4; unsigned long long u[2]; };

__device__ __forceinline__ unsigned long long fma2(unsigned long long a,
                                                   unsigned long long b,
                                                   unsigned long long c) {
    unsigned long long d;
    asm("fma.rn.f32x2 %0, %1, %2, %3;" : "=l"(d) : "l"(a), "l"(b), "l"(c));
    return d;
}
__device__ __forceinline__ float unpack_sum(unsigned long long v) {
    return __uint_as_float((unsigned)(v & 0xffffffffull))
         + __uint_as_float((unsigned)(v >> 32));
}
__device__ __forceinline__ float dot4(float4 a, float4 b) {
    return a.x * b.x + a.y * b.y + a.z * b.z + a.w * b.w;
}

// ---------------------------------------------------------------------------
// k_main: one block per 8-bin tile i0..i0+7.
//  C[t][r'] = P[i0+t] . Q[(i0-61+r') mod N], t in [0,8), r' in [0,132).
//  Register tile 4t x 4r, k-split 8; inner math in packed f32x2 (FFMA2).
//  P tile fully smem-resident; Q streamed in 8 double-buffered chunks.
//  Stats (Q2, A) ride along on tg0 threads. Epilogue identical to R6
//  (verified): kc-reduce -> Xs/sQ2/sA, 240-step eval, last-block argmin.
// ---------------------------------------------------------------------------
__global__ void __launch_bounds__(NTHREADS) k_main(const float* __restrict__ Dq,
                                                   const float* __restrict__ Dp,
                                                   float* __restrict__ out) {
    extern __shared__ __align__(16) float4 dynbuf[];   // 2 x 33792 B Q buffers
    __shared__ float4 Psf[TI][DIM4];                   // 16 KB full P tile
    __shared__ float  Xs[TI][128];                     // kk = k+61 in [0,121]
    __shared__ float  sQ2[RWIN], sA[RWIN], sP2[TI];
    __shared__ unsigned long long wk[NTHREADS / 32];
    __shared__ bool is_last;

    float* Sp = (float*)dynbuf;      // stats partials: [a][kc][r]
    float* Cp = (float*)dynbuf;      // C partials:     [kc][t][r]

    const int i0   = blockIdx.x * TI;
    const int tid  = threadIdx.x;
    const int lane = tid & 31;
    const int warp = tid >> 5;

    const bool act = (tid < NACT);
    const int  rq  = act ? (tid % RQ) : 0;
    const int  grp = act ? (tid / RQ) : 0;     // 0..15
    const int  tg  = grp & 1;                  // t-group: t in [4tg, 4tg+4)
    const int  kc  = grp >> 1;                 // k-split group

    const float4* P4 = (const float4*)Dp;
    const float4* Q4 = (const float4*)Dq;

    // loader roles: 544 threads = 34 row-slots x 16 columns
    const int lr = tid >> 4;                   // 0..33
    const int ll = tid & 15;

    // hoisted per-thread loader indices (constant across chunks)
    int  gq[4];    // global float4 index base (chunk 0, column ll)
    int  sidx[4];  // swizzled store slot within a Q buffer
    bool lok[4];
    #pragma unroll
    for (int p = 0; p < 4; p++) {
        int r = lr + 34 * p;
        lok[p] = (r < RWIN);
        int j  = (i0 - 61 + r) & NMASK;
        gq[p]   = j * DIM4 + ll;
        sidx[p] = r * CHK4 + ((ll + r) & 15);
    }

    // ---- Phase 0: P tile to smem + chunk 0 into buffer 0 ---------------
    for (int idx = tid; idx < TI * DIM4; idx += NTHREADS) {
        ((float4*)Psf)[idx] = P4[i0 * DIM4 + idx];
    }
    {
        float4 pf[4];
        #pragma unroll
        for (int p = 0; p < 4; p++) if (lok[p]) pf[p] = Q4[gq[p]];
        #pragma unroll
        for (int p = 0; p < 4; p++) if (lok[p]) dynbuf[sidx[p]] = pf[p];
    }
    __syncthreads();

    // |P|^2 per bin (warps 0..7)
    if (warp < TI) {
        float4 p0 = Psf[warp][lane], p1 = Psf[warp][lane + 32],
               p2 = Psf[warp][lane + 64], p3 = Psf[warp][lane + 96];
        float s = dot4(p0, p0) + dot4(p1, p1) + dot4(p2, p2) + dot4(p3, p3);
        #pragma unroll
        for (int off = 16; off; off >>= 1) s += __shfl_xor_sync(0xffffffffu, s, off);
        if (lane == 0) sP2[warp] = s;
    }

    // ---- packed accumulators -------------------------------------------
    unsigned long long acc2[4][4];             // [tt][m], f32x2 {even-k, odd-k}
    #pragma unroll
    for (int a = 0; a < 4; a++)
        #pragma unroll
        for (int b = 0; b < 4; b++) acc2[a][b] = 0ull;
    unsigned long long q2a2[4] = {0ull, 0ull, 0ull, 0ull};   // tg0 only
    unsigned long long aaa2[4] = {0ull, 0ull, 0ull, 0ull};   // tg0 only

    // ---- main chunk loop (fully unrolled, double-buffered) -------------
    #pragma unroll
    for (int c = 0; c < NCHUNK; c++) {
        const int buf = c & 1;
        float4 pf[4];
        if (c + 1 < NCHUNK) {
            #pragma unroll
            for (int p = 0; p < 4; p++)
                if (lok[p]) pf[p] = Q4[gq[p] + (c + 1) * CHK4];
        }

        if (act) {
            const float4* Qb = dynbuf + buf * QBUF_F4;
            #pragma unroll
            for (int j2 = 0; j2 < 2; j2++) {
                const int l = 2 * kc + j2;
                F4U2 qv[4];
                #pragma unroll
                for (int m = 0; m < 4; m++) {
                    int r = rq + 33 * m;
                    qv[m].f4 = Qb[r * CHK4 + ((l + r) & 15)];
                }
                F4U2 pv[4];
                #pragma unroll
                for (int tt = 0; tt < 4; tt++)
                    pv[tt].f4 = Psf[tg * 4 + tt][c * CHK4 + l];
                #pragma unroll
                for (int tt = 0; tt < 4; tt++)
                    #pragma unroll
                    for (int m = 0; m < 4; m++) {
                        acc2[tt][m] = fma2(qv[m].u[0], pv[tt].u[0], acc2[tt][m]);
                        acc2[tt][m] = fma2(qv[m].u[1], pv[tt].u[1], acc2[tt][m]);
                    }
                if (tg == 0) {
                    #pragma unroll
                    for (int m = 0; m < 4; m++) {
                        int r  = rq + 33 * m;
                        int pr = (r == 0) ? 0 : (r - 1);   // A[0] never read
                        F4U2 pq; pq.f4 = Qb[pr * CHK4 + ((l + pr) & 15)];
                        q2a2[m] = fma2(qv[m].u[0], qv[m].u[0], q2a2[m]);
                        q2a2[m] = fma2(qv[m].u[1], qv[m].u[1], q2a2[m]);
                        aaa2[m] = fma2(qv[m].u[0], pq.u[0], aaa2[m]);
                        aaa2[m] = fma2(qv[m].u[1], pq.u[1], aaa2[m]);
                    }
                }
            }
        }

        if (c + 1 < NCHUNK) {
            float4* Qn = dynbuf + (buf ^ 1) * QBUF_F4;
            #pragma unroll
            for (int p = 0; p < 4; p++)
                if (lok[p]) Qn[sidx[p]] = pf[p];
        }
        __syncthreads();
    }

    // ---- stats: write tg0 partials, reduce over kc ----------------------
    if (act && tg == 0) {
        #pragma unroll
        for (int m = 0; m < 4; m++) {
            int r = rq + 33 * m;
            Sp[0 * KC * RWIN + kc * RWIN + r] = unpack_sum(q2a2[m]);
            Sp[1 * KC * RWIN + kc * RWIN + r] = unpack_sum(aaa2[m]);
        }
    }
    __syncthreads();
    if (tid < 2 * RWIN) {
        int a = (tid >= RWIN) ? 1 : 0;
        int r = tid - a * RWIN;
        const float* base = Sp + a * KC * RWIN + r;
        float s = 0.f;
        #pragma unroll
        for (int k = 0; k < KC; k++) s += base[k * RWIN];
        if (a == 0) sQ2[r] = s; else sA[r] = s;
    }
    __syncthreads();  // Sp consumed; region reused as Cp next

    // ---- C: write partials, reduce over kc -> Xs band -------------------
    if (act) {
        #pragma unroll
        for (int tt = 0; tt < 4; tt++)
            #pragma unroll
            for (int m = 0; m < 4; m++)
                Cp[kc * TI * RWIN + (tg * 4 + tt) * RWIN + (rq + 33 * m)] =
                    unpack_sum(acc2[tt][m]);
    }
    __syncthreads();
    for (int o = tid; o < TI * RWIN; o += NTHREADS) {
        int t = o / RWIN;
        int r = o - t * RWIN;
        const float* base = Cp + t * RWIN + r;
        float x = 0.f;
        #pragma unroll
        for (int k = 0; k < KC; k++) x += base[k * TI * RWIN];
        int kk = t + 122 - r;          // k + 61
        if ((unsigned)kk < (unsigned)NK) Xs[t][kk] = x;
    }
    __syncthreads();

    // ---- Phase 3: evaluate 240 steps over this block's 8 bins -----------
    if (tid < NSTEPS) {
        const int s = tid;
        int k0, k1; float alpha; bool pos;
        if (s < 120) {                         // steps 0.0, 0.5, ..., 59.5
            k0 = s >> 1; k1 = k0 + 1;
            alpha = (s & 1) ? 0.5f : 0.0f;
            pos = true;
        } else {                               // steps -1.0, -1.5, ..., -60.5
            int u = s - 120;
            k0 = -(1 + (u >> 1)); k1 = k0 - 1;
            alpha = (u & 1) ? 0.5f : 0.0f;
            pos = false;
        }
        const float w0 = 1.0f - alpha, w1 = alpha;
        const float w00 = w0 * w0, w11 = w1 * w1, w01 = 2.0f * w0 * w1;
        float accs = 0.0f;
        #pragma unroll
        for (int t = 0; t < TI; t++) {
            int j0r = t + 61 - k0;             // window-relative row of roll k0
            int j1r = t + 61 - k1;
            float adot = pos ? sA[j0r] : sA[j1r];   // Q[j0].Q[j1] adjacency
            float x0 = Xs[t][k0 + 61];
            float x1 = Xs[t][k1 + 61];
            float r2 = sP2[t] + w00 * sQ2[j0r] + w11 * sQ2[j1r]
                     + w01 * adot - 2.0f * (w0 * x0 + w1 * x1);
            accs += sqrtf(fmaxf(r2, 0.0f));
        }
        g_bpart[s * NBLK + blockIdx.x] = accs;
    }

    // ---- Phase 4: last block reduces everything (no second launch) ------
    __threadfence();
    __syncthreads();                 // all phase-3 stores of this block issued
    if (tid == 0) {
        unsigned t = atomicAdd(&g_ticket, 1u);
        is_last = (t == (unsigned)(NBLK - 1));
        if (is_last) g_ticket = 0;   // reset for next graph replay
    }
    __syncthreads();
    if (!is_last) return;

    // Deterministic mean + argmin (identical summation order every launch).
    const int s    = tid >> 1;       // 2 threads per step, 64 partials each
    const int half = tid & 1;
    unsigned long long key = ~0ull;
    if (s < NSTEPS) {
        const float4* bp = (const float4*)(g_bpart + s * NBLK + half * (NBLK / 2));
        float s0 = 0.f, s1 = 0.f, s2 = 0.f, s3 = 0.f;
        #pragma unroll
        for (int c = 0; c < NBLK / 8; c += 4) {
            float4 v0 = bp[c], v1 = bp[c + 1], v2 = bp[c + 2], v3 = bp[c + 3];
            s0 += v0.x + v0.y + v0.z + v0.w;
            s1 += v1.x + v1.y + v1.z + v1.w;
            s2 += v2.x + v2.y + v2.z + v2.w;
            s3 += v3.x + v3.y + v3.z + v3.w;
        }
        float mine = (s0 + s1) + (s2 + s3);
        float tot  = mine + __shfl_xor_sync(0xffffffffu, mine, 1);
        float dist = tot * (1.0f / (float)N_BINS);
        // positive-float bit order == numeric order; low 32 bits = index so
        // ties resolve to the smallest step index (matches jnp.argmin).
        key = ((unsigned long long)__float_as_uint(dist) << 32) | (unsigned)s;
    }
    #pragma unroll
    for (int off = 16; off; off >>= 1) {
        unsigned long long o = __shfl_xor_sync(0xffffffffu, key, off);
        if (o < key) key = o;
    }
    if (lane == 0) wk[warp] = key;
    __syncthreads();
    if (tid == 0) {
        unsigned long long best = wk[0];
        #pragma unroll
        for (int w = 1; w < NTHREADS / 32; w++) if (wk[w] < best) best = wk[w];
        int bi = (int)(best & 0xffffffffull);
        float dist = __uint_as_float((unsigned)(best >> 32));
        float step = (bi < 120) ? 0.5f * (float)bi : -(1.0f + 0.5f * (float)(bi - 120));
        out[0] = step;
        out[1] = dist;
    }
}

extern "C" void kernel_launch(void* const* d_in, const int* in_sizes, int n_in,
                              void* d_out, int out_size) {
    const float* Dq = (const float*)d_in[0];  // D_q [1024, 512]
    const float* Dp = (const float*)d_in[1];  // D_p [1024, 512]
    float* out = (float*)d_out;

    cudaFuncSetAttribute(k_main, cudaFuncAttributeMaxDynamicSharedMemorySize,
                         DYN_BYTES);
    k_main<<<NBLK, NTHREADS, DYN_BYTES>>>(Dq, Dp, out);
}